// round 8
// baseline (speedup 1.0000x reference)
#include <cuda_runtime.h>
#include <cuda_bf16.h>
#include <cstdint>

#define CC 256
#define HH 128
#define WW 128
#define HWSZ (HH*WW)
#define WKP_W 132                  // wk pitch in words (264 bf16)
#define XBP   264                  // xbw pitch in words per c2 row (256 pix + 8 pad)

// shared layout in 4-byte units
#define SM_WK   0                          // [64][132] words  = 8448
#define SM_XBW  8448                       // [32][264] words  = 8448
#define SM_KQS  16896                      // [2 grp][256 pix][4 s] = 2048
#define SM_WBUF 18944                      // [16 win][68] = 1088
#define SMEM_WORDS 20032
#define SMEM_BYTES (SMEM_WORDS*4)          // 80128

__device__ __forceinline__ unsigned pack_bf2(float lo, float hi) {
    __nv_bfloat162 h = __floats2bfloat162_rn(lo, hi);
    return *reinterpret_cast<unsigned*>(&h);
}

__global__ __launch_bounds__(512, 2) void frac_fused_kernel(
    const float* __restrict__ x,
    const float* __restrict__ w_key,
    const float* __restrict__ w_sim,
    float* __restrict__ out)
{
    extern __shared__ float S[];
    unsigned* wkw  = (unsigned*)(S + SM_WK);        // [key][132] words
    unsigned* xbw  = (unsigned*)(S + SM_XBW);       // [c2l][264] words (c_even,c_odd)
    float*    kqs  = S + SM_KQS;                    // [grp][pix][s]
    float*    wbuf = S + SM_WBUF;                   // [win][16p][4s] pitch 68

    const int tid  = threadIdx.x;
    const int wp   = tid >> 5;
    const int lane = tid & 31;
    const int gid  = lane >> 2;        // 0..7
    const int ctid = lane & 3;         // 0..3
    const int grpM = wp & 1;           // 2 m-groups
    const int mtb  = grpM * 32;        // key rows mtb..mtb+31
    const int pixb = (wp >> 1) * 32;   // 8 pixel groups of 32
    const int wh = blockIdx.x;         // 0..1
    const int hh = blockIdx.y;         // 0..31
    const int n  = blockIdx.z;         // 0..15

    const float* xpix = x + ((size_t)n*CC)*HWSZ + (size_t)(hh*4)*WW + wh*64;

    // ---- prologue: w_key -> bf16 smem [key][k] ----
    for (int i = tid; i < 64*128; i += 512) {
        int k = i >> 7, c2 = i & 127;
        float2 v = *(const float2*)(w_key + k*256 + c2*2);
        wkw[k*WKP_W + c2] = pack_bf2(v.x, v.y);
    }

    // per-lane ldmatrix address for A (row = key, 16B col-half)
    const uint32_t wk_sb = (uint32_t)__cvta_generic_to_shared(S + SM_WK);
    const uint32_t a_lane_addr = wk_sb
        + (uint32_t)(((mtb + (lane & 15)) * (WKP_W*2) + (lane >> 4) * 8) * 2);

    float acc[2][4][4];
    #pragma unroll
    for (int t = 0; t < 2; t++)
        #pragma unroll
        for (int i = 0; i < 4; i++)
            #pragma unroll
            for (int j = 0; j < 4; j++) acc[t][i][j] = 0.f;

    #pragma unroll
    for (int ch = 0; ch < 4; ch++) {
        if (ch) __syncthreads();               // previous chunk's B reads done

        // ---- convert channels [64ch, 64ch+64) x 256 pixels -> bf16 pairs ----
        #pragma unroll
        for (int j = 0; j < 4; j++) {
            int id  = j*512 + tid;             // 0..2047 : c2l(32) x p4(64)
            int c2l = id >> 6, p4 = id & 63;
            int r = p4 >> 4, w4 = p4 & 15;
            const float* g = xpix + (size_t)(64*ch + 2*c2l)*HWSZ + r*WW + w4*4;
            float4 fa = *(const float4*)g;
            float4 fb = *(const float4*)(g + HWSZ);
            uint4 wv;
            wv.x = pack_bf2(fa.x, fb.x);
            wv.y = pack_bf2(fa.y, fb.y);
            wv.z = pack_bf2(fa.z, fb.z);
            wv.w = pack_bf2(fa.w, fb.w);
            *(uint4*)(xbw + c2l*XBP + r*64 + w4*4) = wv;
        }
        __syncthreads();                       // xbw ready (also orders prologue wk)

        // ---- GEMM: 4 k16 slabs; warp tile M=32, N=32; B hoisted across t ----
        #pragma unroll
        for (int ktl = 0; ktl < 4; ktl++) {
            unsigned b[4][2];
            const int b0row = (ktl*8 + ctid)     * XBP;
            const int b1row = (ktl*8 + ctid + 4) * XBP;
            #pragma unroll
            for (int nt = 0; nt < 4; nt++) {
                int pix = pixb + nt*8 + gid;
                b[nt][0] = xbw[b0row + pix];
                b[nt][1] = xbw[b1row + pix];
            }
            #pragma unroll
            for (int t = 0; t < 2; t++) {
                unsigned a0, a1, a2, a3;
                asm volatile(
                    "ldmatrix.sync.aligned.m8n8.x4.shared.b16 {%0,%1,%2,%3}, [%4];"
                    : "=r"(a0), "=r"(a1), "=r"(a2), "=r"(a3)
                    : "r"(a_lane_addr + (unsigned)(t*16*WKP_W*4 + (ch*4 + ktl)*32)));
                #pragma unroll
                for (int nt = 0; nt < 4; nt++) {
                    asm volatile(
                        "mma.sync.aligned.m16n8k16.row.col.f32.bf16.bf16.f32 "
                        "{%0,%1,%2,%3}, {%4,%5,%6,%7}, {%8,%9}, {%0,%1,%2,%3};"
                        : "+f"(acc[t][nt][0]), "+f"(acc[t][nt][1]),
                          "+f"(acc[t][nt][2]), "+f"(acc[t][nt][3])
                        : "r"(a0), "r"(a1), "r"(a2), "r"(a3),
                          "r"(b[nt][0]), "r"(b[nt][1]));
                }
            }
        }
    }

    // ---- epilogue kq: relu + w_sim contraction from accumulators ----
    // lane's 4 key rows: mtb+gid + {0, 8, 16, 24}
    float ws[4][4];
    #pragma unroll
    for (int s = 0; s < 4; s++) {
        ws[0][s] = w_sim[s*64 + mtb + gid];
        ws[1][s] = w_sim[s*64 + mtb + gid + 8];
        ws[2][s] = w_sim[s*64 + mtb + gid + 16];
        ws[3][s] = w_sim[s*64 + mtb + gid + 24];
    }
    #pragma unroll
    for (int nt = 0; nt < 4; nt++) {
        float part[2][4];
        #pragma unroll
        for (int u = 0; u < 2; u++) {
            float v0 = fmaxf(acc[0][nt][u],     0.f);   // row mtb+gid
            float v1 = fmaxf(acc[0][nt][2 + u], 0.f);   // +8
            float v2 = fmaxf(acc[1][nt][u],     0.f);   // +16
            float v3 = fmaxf(acc[1][nt][2 + u], 0.f);   // +24
            #pragma unroll
            for (int s = 0; s < 4; s++)
                part[u][s] = ws[0][s]*v0 + ws[1][s]*v1 + ws[2][s]*v2 + ws[3][s]*v3;
        }
        #pragma unroll
        for (int off = 4; off <= 16; off <<= 1)
            #pragma unroll
            for (int u = 0; u < 2; u++)
                #pragma unroll
                for (int s = 0; s < 4; s++)
                    part[u][s] += __shfl_xor_sync(0xffffffffu, part[u][s], off);
        if (gid == 0) {
            #pragma unroll
            for (int u = 0; u < 2; u++) {
                int pix = pixb + nt*8 + 2*ctid + u;
                *(float4*)(kqs + grpM*1024 + pix*4) = make_float4(
                    part[u][0], part[u][1], part[u][2], part[u][3]);
            }
        }
    }
    __syncthreads();                           // kqs complete

    // ---- per-window softmax (16 windows x 4 s = 64 threads) ----
    if (tid < 64) {
        int win = tid >> 2, s = tid & 3;
        float v[16], m = -1e30f;
        #pragma unroll
        for (int r0 = 0; r0 < 4; r0++)
            #pragma unroll
            for (int j = 0; j < 4; j++) {
                int pix = r0*64 + win*4 + j;
                float t = (kqs[pix*4 + s] + kqs[1024 + pix*4 + s]) * 0.25f;
                v[r0*4+j] = t;
                m = fmaxf(m, t);
            }
        float sum = 0.f;
        #pragma unroll
        for (int p = 0; p < 16; p++) { float e = __expf(v[p]-m); v[p] = e; sum += e; }
        float inv = 1.f / sum;
        #pragma unroll
        for (int p = 0; p < 16; p++) wbuf[win*68 + p*4 + s] = v[p]*inv;
    }
    __syncthreads();                           // wbuf ready

    // ---- aggregation: lane = (win,sp); warp strides channels ----
    {
        const int sp  = tid & 1;
        const int win = (tid >> 1) & 15;
        float2 w2[16];
        #pragma unroll
        for (int p = 0; p < 16; p++)
            w2[p] = *(const float2*)(wbuf + win*68 + p*4 + 2*sp);
        const int ww = wh*16 + win;
        const float* gw = xpix + win*4;
        #pragma unroll 4
        for (int it = 0; it < 16; it++) {
            int c = it*16 + wp;
            const float* xc = gw + (size_t)c*HWSZ;
            float o0 = 0.f, o1 = 0.f;
            #pragma unroll
            for (int r0 = 0; r0 < 4; r0++) {
                float4 xv = *(const float4*)(xc + r0*WW);
                o0 += xv.x*w2[r0*4+0].x + xv.y*w2[r0*4+1].x
                    + xv.z*w2[r0*4+2].x + xv.w*w2[r0*4+3].x;
                o1 += xv.x*w2[r0*4+0].y + xv.y*w2[r0*4+1].y
                    + xv.z*w2[r0*4+2].y + xv.w*w2[r0*4+3].y;
            }
            float2* op = (float2*)(out + ((size_t)(n*CC + c)*64 + (2*hh+sp))*64 + 2*ww);
            *op = make_float2(o0, o1);
        }
    }
}

extern "C" void kernel_launch(void* const* d_in, const int* in_sizes, int n_in,
                              void* d_out, int out_size)
{
    (void)in_sizes; (void)n_in; (void)out_size;
    const float* x  = (const float*)d_in[0];
    const float* wk = (const float*)d_in[1];
    const float* ws = (const float*)d_in[2];
    float* out = (float*)d_out;

    cudaFuncSetAttribute(frac_fused_kernel,
                         cudaFuncAttributeMaxDynamicSharedMemorySize, SMEM_BYTES);
    frac_fused_kernel<<<dim3(2, 32, 16), 512, SMEM_BYTES>>>(x, wk, ws, out);
}

// round 9
// speedup vs baseline: 1.4489x; 1.4489x over previous
#include <cuda_runtime.h>
#include <cuda_bf16.h>
#include <cstdint>

#define CC 256
#define HH 128
#define WW 128
#define HWSZ (HH*WW)
#define WKP_W 132                  // wk pitch in words (264 bf16)
#define XBP   136                  // xbw pitch in words per c2 row (128 pix + 8 pad)

// shared layout in 4-byte units
#define SM_WK   0                          // [64][132] words = 8448
#define SM_XBW  8448                       // [32][136] words = 4352
#define SM_KQS  SM_XBW                     // alias: [2 grp][128 pix][4 s] = 1024
#define SM_WBUF (SM_XBW + 1024)            // alias: [8 win][68] = 544
#define SMEM_WORDS (SM_XBW + 4352)         // 12800
#define SMEM_BYTES (SMEM_WORDS*4)          // 51200

__device__ __forceinline__ unsigned pack_bf2(float lo, float hi) {
    __nv_bfloat162 h = __floats2bfloat162_rn(lo, hi);
    return *reinterpret_cast<unsigned*>(&h);
}

__global__ __launch_bounds__(256, 4) void frac_fused_kernel(
    const float* __restrict__ x,
    const float* __restrict__ w_key,
    const float* __restrict__ w_sim,
    float* __restrict__ out)
{
    extern __shared__ float S[];
    unsigned* wkw  = (unsigned*)(S + SM_WK);        // [key][132] words
    unsigned* xbw  = (unsigned*)(S + SM_XBW);       // [c2l][136] words (c_even,c_odd)
    float*    kqs  = S + SM_KQS;                    // alias after GEMM: [grp][128][4]
    float*    wbuf = S + SM_WBUF;                   // alias: [8 win][68]

    const int tid  = threadIdx.x;
    const int wp   = tid >> 5;         // 0..7
    const int lane = tid & 31;
    const int gid  = lane >> 2;        // 0..7
    const int ctid = lane & 3;         // 0..3
    const int grpM = wp & 1;           // 2 m-groups
    const int mtb  = grpM * 32;        // key rows mtb..mtb+31
    const int pixb = (wp >> 1) * 32;   // 4 pixel groups of 32
    const int wh = blockIdx.x;         // 0..3  (32-col quarter)
    const int hh = blockIdx.y;         // 0..31
    const int n  = blockIdx.z;         // 0..15

    const float* xpix = x + ((size_t)n*CC)*HWSZ + (size_t)(hh*4)*WW + wh*32;

    // ---- prologue: w_key -> bf16 smem [key][k] ----
    for (int i = tid; i < 64*128; i += 256) {
        int k = i >> 7, c2 = i & 127;
        float2 v = *(const float2*)(w_key + k*256 + c2*2);
        wkw[k*WKP_W + c2] = pack_bf2(v.x, v.y);
    }

    // per-lane ldmatrix address for A (row = key, 16B col-half)
    const uint32_t wk_sb = (uint32_t)__cvta_generic_to_shared(S + SM_WK);
    const uint32_t a_lane_addr = wk_sb
        + (uint32_t)(((mtb + (lane & 15)) * (WKP_W*2) + (lane >> 4) * 8) * 2);

    float acc[2][4][4];
    #pragma unroll
    for (int t = 0; t < 2; t++)
        #pragma unroll
        for (int i = 0; i < 4; i++)
            #pragma unroll
            for (int j = 0; j < 4; j++) acc[t][i][j] = 0.f;

    #pragma unroll 1
    for (int ch = 0; ch < 4; ch++) {
        __syncthreads();                       // prev chunk's B reads done (orders prologue too)

        // ---- convert channels [64ch, 64ch+64) x 128 pixels -> bf16 pairs ----
        #pragma unroll
        for (int j = 0; j < 4; j++) {
            int id  = j*256 + tid;             // 0..1023 : c2l(32) x p4(32)
            int c2l = id >> 5, p4 = id & 31;
            int r = p4 >> 3, w4 = p4 & 7;
            const float* g = xpix + (size_t)(64*ch + 2*c2l)*HWSZ + r*WW + w4*4;
            float4 fa = *(const float4*)g;
            float4 fb = *(const float4*)(g + HWSZ);
            uint4 wv;
            wv.x = pack_bf2(fa.x, fb.x);
            wv.y = pack_bf2(fa.y, fb.y);
            wv.z = pack_bf2(fa.z, fb.z);
            wv.w = pack_bf2(fa.w, fb.w);
            *(uint4*)(xbw + c2l*XBP + r*32 + w4*4) = wv;
        }
        __syncthreads();                       // xbw ready

        // ---- GEMM: 4 k16 slabs; warp tile M=32, N=32; B hoisted across t ----
        #pragma unroll
        for (int ktl = 0; ktl < 4; ktl++) {
            unsigned b[4][2];
            const int b0row = (ktl*8 + ctid)     * XBP;
            const int b1row = (ktl*8 + ctid + 4) * XBP;
            #pragma unroll
            for (int nt = 0; nt < 4; nt++) {
                int pix = pixb + nt*8 + gid;
                b[nt][0] = xbw[b0row + pix];
                b[nt][1] = xbw[b1row + pix];
            }
            #pragma unroll
            for (int t = 0; t < 2; t++) {
                unsigned a0, a1, a2, a3;
                asm volatile(
                    "ldmatrix.sync.aligned.m8n8.x4.shared.b16 {%0,%1,%2,%3}, [%4];"
                    : "=r"(a0), "=r"(a1), "=r"(a2), "=r"(a3)
                    : "r"(a_lane_addr + (unsigned)(t*16*WKP_W*4) + (unsigned)((ch*4 + ktl)*32)));
                #pragma unroll
                for (int nt = 0; nt < 4; nt++) {
                    asm volatile(
                        "mma.sync.aligned.m16n8k16.row.col.f32.bf16.bf16.f32 "
                        "{%0,%1,%2,%3}, {%4,%5,%6,%7}, {%8,%9}, {%0,%1,%2,%3};"
                        : "+f"(acc[t][nt][0]), "+f"(acc[t][nt][1]),
                          "+f"(acc[t][nt][2]), "+f"(acc[t][nt][3])
                        : "r"(a0), "r"(a1), "r"(a2), "r"(a3),
                          "r"(b[nt][0]), "r"(b[nt][1]));
                }
            }
        }
    }
    __syncthreads();                           // all B reads done; xbw region reusable as kqs

    // ---- epilogue kq: relu + w_sim contraction from accumulators ----
    // lane's 4 key rows: mtb+gid + {0, 8, 16, 24}
    float ws[4][4];
    #pragma unroll
    for (int s = 0; s < 4; s++) {
        ws[0][s] = w_sim[s*64 + mtb + gid];
        ws[1][s] = w_sim[s*64 + mtb + gid + 8];
        ws[2][s] = w_sim[s*64 + mtb + gid + 16];
        ws[3][s] = w_sim[s*64 + mtb + gid + 24];
    }
    #pragma unroll
    for (int nt = 0; nt < 4; nt++) {
        float part[2][4];
        #pragma unroll
        for (int u = 0; u < 2; u++) {
            float v0 = fmaxf(acc[0][nt][u],     0.f);   // row mtb+gid
            float v1 = fmaxf(acc[0][nt][2 + u], 0.f);   // +8
            float v2 = fmaxf(acc[1][nt][u],     0.f);   // +16
            float v3 = fmaxf(acc[1][nt][2 + u], 0.f);   // +24
            #pragma unroll
            for (int s = 0; s < 4; s++)
                part[u][s] = ws[0][s]*v0 + ws[1][s]*v1 + ws[2][s]*v2 + ws[3][s]*v3;
        }
        #pragma unroll
        for (int off = 4; off <= 16; off <<= 1)
            #pragma unroll
            for (int u = 0; u < 2; u++)
                #pragma unroll
                for (int s = 0; s < 4; s++)
                    part[u][s] += __shfl_xor_sync(0xffffffffu, part[u][s], off);
        if (gid == 0) {
            #pragma unroll
            for (int u = 0; u < 2; u++) {
                int pix = pixb + nt*8 + 2*ctid + u;
                *(float4*)(kqs + grpM*512 + pix*4) = make_float4(
                    part[u][0], part[u][1], part[u][2], part[u][3]);
            }
        }
    }
    __syncthreads();                           // kqs complete

    // ---- per-window softmax (8 windows x 4 s = 32 threads) ----
    if (tid < 32) {
        int win = tid >> 2, s = tid & 3;
        float v[16], m = -1e30f;
        #pragma unroll
        for (int r0 = 0; r0 < 4; r0++)
            #pragma unroll
            for (int j = 0; j < 4; j++) {
                int pix = r0*32 + win*4 + j;
                float t = (kqs[pix*4 + s] + kqs[512 + pix*4 + s]) * 0.25f;
                v[r0*4+j] = t;
                m = fmaxf(m, t);
            }
        float sum = 0.f;
        #pragma unroll
        for (int p = 0; p < 16; p++) { float e = __expf(v[p]-m); v[p] = e; sum += e; }
        float inv = 1.f / sum;
        #pragma unroll
        for (int p = 0; p < 16; p++) wbuf[win*68 + p*4 + s] = v[p]*inv;
    }
    __syncthreads();                           // wbuf ready

    // ---- aggregation: lane = (sp, win, c-slot); 16 channel iterations ----
    {
        const int sp  = tid & 1;
        const int win = (tid >> 1) & 7;
        float2 w2[16];
        #pragma unroll
        for (int p = 0; p < 16; p++)
            w2[p] = *(const float2*)(wbuf + win*68 + p*4 + 2*sp);
        const int ww = wh*8 + win;
        const float* gw = xpix + win*4;
        #pragma unroll 4
        for (int it = 0; it < 16; it++) {
            int c = it*16 + (tid >> 4);
            const float* xc = gw + (size_t)c*HWSZ;
            float o0 = 0.f, o1 = 0.f;
            #pragma unroll
            for (int r0 = 0; r0 < 4; r0++) {
                float4 xv = *(const float4*)(xc + r0*WW);
                o0 += xv.x*w2[r0*4+0].x + xv.y*w2[r0*4+1].x
                    + xv.z*w2[r0*4+2].x + xv.w*w2[r0*4+3].x;
                o1 += xv.x*w2[r0*4+0].y + xv.y*w2[r0*4+1].y
                    + xv.z*w2[r0*4+2].y + xv.w*w2[r0*4+3].y;
            }
            float2* op = (float2*)(out + ((size_t)(n*CC + c)*64 + (2*hh+sp))*64 + 2*ww);
            *op = make_float2(o0, o1);
        }
    }
}

extern "C" void kernel_launch(void* const* d_in, const int* in_sizes, int n_in,
                              void* d_out, int out_size)
{
    (void)in_sizes; (void)n_in; (void)out_size;
    const float* x  = (const float*)d_in[0];
    const float* wk = (const float*)d_in[1];
    const float* ws = (const float*)d_in[2];
    float* out = (float*)d_out;

    cudaFuncSetAttribute(frac_fused_kernel,
                         cudaFuncAttributeMaxDynamicSharedMemorySize, SMEM_BYTES);
    frac_fused_kernel<<<dim3(4, 32, 16), 256, SMEM_BYTES>>>(x, wk, ws, out);
}

// round 10
// speedup vs baseline: 1.5322x; 1.0574x over previous
#include <cuda_runtime.h>
#include <cuda_bf16.h>
#include <cstdint>

#define CC 256
#define HH 128
#define WW 128
#define HWSZ (HH*WW)
#define WKP_W 132                  // wk pitch in words (264 bf16)
#define XBP   136                  // xbw pitch in words per c2 row (128 pix + 8 pad)

// shared layout in 4-byte units
#define SM_WK   0                          // [64][132] words = 8448
#define SM_XBW  8448                       // [32][136] words = 4352
#define SM_KQS  SM_XBW                     // alias: [2 grp][128 pix][4 s] = 1024
#define SM_WBUF (SM_XBW + 1024)            // alias: [8 win][68] = 544
#define SMEM_WORDS (SM_XBW + 4352)         // 12800
#define SMEM_BYTES (SMEM_WORDS*4)          // 51200

// pre-converted, pre-padded bf16 w_key image [64][132] words
__device__ unsigned g_wkb[64*WKP_W];

__device__ __forceinline__ unsigned pack_bf2(float lo, float hi) {
    __nv_bfloat162 h = __floats2bfloat162_rn(lo, hi);
    return *reinterpret_cast<unsigned*>(&h);
}

#define PACK2(o, lo, hi) asm("mov.b64 %0, {%1, %2};" : "=l"(o) : "f"(lo), "f"(hi))
#define UNPACK2(lo, hi, i) asm("mov.b64 {%0, %1}, %2;" : "=f"(lo), "=f"(hi) : "l"(i))
#define FMA2(o, a, b) asm("fma.rn.f32x2 %0, %1, %2, %0;" : "+l"(o) : "l"(a), "l"(b))

__global__ void prep_wkey(const float* __restrict__ w_key)
{
    int i = blockIdx.x*256 + threadIdx.x;
    if (i < 64*WKP_W) {
        int k = i / WKP_W, c2 = i % WKP_W;
        unsigned v = 0;
        if (c2 < 128) {
            float2 f = *(const float2*)(w_key + k*256 + c2*2);
            v = pack_bf2(f.x, f.y);
        }
        g_wkb[i] = v;
    }
}

__global__ __launch_bounds__(256, 4) void frac_fused_kernel(
    const float* __restrict__ x,
    const float* __restrict__ w_sim,
    float* __restrict__ out)
{
    extern __shared__ float S[];
    unsigned* wkw  = (unsigned*)(S + SM_WK);        // [key][132] words
    unsigned* xbw  = (unsigned*)(S + SM_XBW);       // [c2l][136] words (c_even,c_odd)
    float*    kqs  = S + SM_KQS;                    // alias after GEMM: [grp][128][4]
    float*    wbuf = S + SM_WBUF;                   // alias: [8 win][68]

    const int tid  = threadIdx.x;
    const int wp   = tid >> 5;         // 0..7
    const int lane = tid & 31;
    const int gid  = lane >> 2;        // 0..7
    const int ctid = lane & 3;         // 0..3
    const int grpM = wp & 1;           // 2 m-groups
    const int mtb  = grpM * 32;        // key rows mtb..mtb+31
    const int pixb = (wp >> 1) * 32;   // 4 pixel groups of 32
    const int wh = blockIdx.x;         // 0..3  (32-col quarter)
    const int hh = blockIdx.y;         // 0..31
    const int n  = blockIdx.z;         // 0..15

    const float* xpix = x + ((size_t)n*CC)*HWSZ + (size_t)(hh*4)*WW + wh*32;

    // ---- prologue: copy pre-converted bf16 w_key image into smem ----
    {
        const uint4* src = (const uint4*)g_wkb;
        uint4*       dst = (uint4*)wkw;
        for (int i = tid; i < (64*WKP_W)/4; i += 256) dst[i] = src[i];
    }

    // per-lane ldmatrix address for A (row = key, 16B col-half)
    const uint32_t wk_sb = (uint32_t)__cvta_generic_to_shared(S + SM_WK);
    const uint32_t a_lane_addr = wk_sb
        + (uint32_t)(((mtb + (lane & 15)) * (WKP_W*2) + (lane >> 4) * 8) * 2);

    float acc[2][4][4];
    #pragma unroll
    for (int t = 0; t < 2; t++)
        #pragma unroll
        for (int i = 0; i < 4; i++)
            #pragma unroll
            for (int j = 0; j < 4; j++) acc[t][i][j] = 0.f;

    #pragma unroll 1
    for (int ch = 0; ch < 4; ch++) {
        __syncthreads();                       // prev chunk's B reads done (orders prologue too)

        // ---- convert channels [64ch, 64ch+64) x 128 pixels -> bf16 pairs ----
        #pragma unroll
        for (int j = 0; j < 4; j++) {
            int id  = j*256 + tid;             // 0..1023 : c2l(32) x p4(32)
            int c2l = id >> 5, p4 = id & 31;
            int r = p4 >> 3, w4 = p4 & 7;
            const float* g = xpix + (size_t)(64*ch + 2*c2l)*HWSZ + r*WW + w4*4;
            float4 fa = *(const float4*)g;
            float4 fb = *(const float4*)(g + HWSZ);
            uint4 wv;
            wv.x = pack_bf2(fa.x, fb.x);
            wv.y = pack_bf2(fa.y, fb.y);
            wv.z = pack_bf2(fa.z, fb.z);
            wv.w = pack_bf2(fa.w, fb.w);
            *(uint4*)(xbw + c2l*XBP + r*32 + w4*4) = wv;
        }
        __syncthreads();                       // xbw ready

        // ---- GEMM: 4 k16 slabs; warp tile M=32, N=32; B hoisted across t ----
        #pragma unroll
        for (int ktl = 0; ktl < 4; ktl++) {
            unsigned b[4][2];
            const int b0row = (ktl*8 + ctid)     * XBP;
            const int b1row = (ktl*8 + ctid + 4) * XBP;
            #pragma unroll
            for (int nt = 0; nt < 4; nt++) {
                int pix = pixb + nt*8 + gid;
                b[nt][0] = xbw[b0row + pix];
                b[nt][1] = xbw[b1row + pix];
            }
            #pragma unroll
            for (int t = 0; t < 2; t++) {
                unsigned a0, a1, a2, a3;
                asm volatile(
                    "ldmatrix.sync.aligned.m8n8.x4.shared.b16 {%0,%1,%2,%3}, [%4];"
                    : "=r"(a0), "=r"(a1), "=r"(a2), "=r"(a3)
                    : "r"(a_lane_addr + (unsigned)(t*16*WKP_W*4) + (unsigned)((ch*4 + ktl)*32)));
                #pragma unroll
                for (int nt = 0; nt < 4; nt++) {
                    asm volatile(
                        "mma.sync.aligned.m16n8k16.row.col.f32.bf16.bf16.f32 "
                        "{%0,%1,%2,%3}, {%4,%5,%6,%7}, {%8,%9}, {%0,%1,%2,%3};"
                        : "+f"(acc[t][nt][0]), "+f"(acc[t][nt][1]),
                          "+f"(acc[t][nt][2]), "+f"(acc[t][nt][3])
                        : "r"(a0), "r"(a1), "r"(a2), "r"(a3),
                          "r"(b[nt][0]), "r"(b[nt][1]));
                }
            }
        }
    }
    __syncthreads();                           // all B reads done; xbw region reusable as kqs

    // ---- epilogue kq: relu + w_sim contraction from accumulators ----
    float ws[4][4];
    #pragma unroll
    for (int s = 0; s < 4; s++) {
        ws[0][s] = w_sim[s*64 + mtb + gid];
        ws[1][s] = w_sim[s*64 + mtb + gid + 8];
        ws[2][s] = w_sim[s*64 + mtb + gid + 16];
        ws[3][s] = w_sim[s*64 + mtb + gid + 24];
    }
    #pragma unroll
    for (int nt = 0; nt < 4; nt++) {
        float part[2][4];
        #pragma unroll
        for (int u = 0; u < 2; u++) {
            float v0 = fmaxf(acc[0][nt][u],     0.f);
            float v1 = fmaxf(acc[0][nt][2 + u], 0.f);
            float v2 = fmaxf(acc[1][nt][u],     0.f);
            float v3 = fmaxf(acc[1][nt][2 + u], 0.f);
            #pragma unroll
            for (int s = 0; s < 4; s++)
                part[u][s] = ws[0][s]*v0 + ws[1][s]*v1 + ws[2][s]*v2 + ws[3][s]*v3;
        }
        #pragma unroll
        for (int off = 4; off <= 16; off <<= 1)
            #pragma unroll
            for (int u = 0; u < 2; u++)
                #pragma unroll
                for (int s = 0; s < 4; s++)
                    part[u][s] += __shfl_xor_sync(0xffffffffu, part[u][s], off);
        if (gid == 0) {
            #pragma unroll
            for (int u = 0; u < 2; u++) {
                int pix = pixb + nt*8 + 2*ctid + u;
                *(float4*)(kqs + grpM*512 + pix*4) = make_float4(
                    part[u][0], part[u][1], part[u][2], part[u][3]);
            }
        }
    }
    __syncthreads();                           // kqs complete

    // ---- per-window softmax (8 windows x 4 s = 32 threads) ----
    if (tid < 32) {
        int win = tid >> 2, s = tid & 3;
        float v[16], m = -1e30f;
        #pragma unroll
        for (int r0 = 0; r0 < 4; r0++)
            #pragma unroll
            for (int j = 0; j < 4; j++) {
                int pix = r0*32 + win*4 + j;
                float t = (kqs[pix*4 + s] + kqs[512 + pix*4 + s]) * 0.25f;
                v[r0*4+j] = t;
                m = fmaxf(m, t);
            }
        float sum = 0.f;
        #pragma unroll
        for (int p = 0; p < 16; p++) { float e = __expf(v[p]-m); v[p] = e; sum += e; }
        float inv = 1.f / sum;
        #pragma unroll
        for (int p = 0; p < 16; p++) wbuf[win*68 + p*4 + s] = v[p]*inv;
    }
    __syncthreads();                           // wbuf ready

    // ---- aggregation: thread = (win, c-slot); all 4 outputs per window ----
    // x rows read ONCE per CTA; packed f32x2 FMA for (s0,s1)/(s2,s3) pairs.
    {
        const int win   = tid & 7;
        const int cslot = tid >> 3;            // 0..31
        const int ww    = wh*8 + win;
        unsigned long long o01[8], o23[8];
        #pragma unroll
        for (int it = 0; it < 8; it++) { o01[it] = 0ull; o23[it] = 0ull; }

        #pragma unroll
        for (int r0 = 0; r0 < 4; r0++) {
            unsigned long long w01[4], w23[4];
            #pragma unroll
            for (int j = 0; j < 4; j++) {
                float4 wv = *(const float4*)(wbuf + win*68 + (r0*4 + j)*4);
                PACK2(w01[j], wv.x, wv.y);
                PACK2(w23[j], wv.z, wv.w);
            }
            #pragma unroll
            for (int it = 0; it < 8; it++) {
                int c = it*32 + cslot;
                float4 xv = *(const float4*)(xpix + (size_t)c*HWSZ + r0*WW + win*4);
                unsigned long long xp;
                PACK2(xp, xv.x, xv.x); FMA2(o01[it], xp, w01[0]); FMA2(o23[it], xp, w23[0]);
                PACK2(xp, xv.y, xv.y); FMA2(o01[it], xp, w01[1]); FMA2(o23[it], xp, w23[1]);
                PACK2(xp, xv.z, xv.z); FMA2(o01[it], xp, w01[2]); FMA2(o23[it], xp, w23[2]);
                PACK2(xp, xv.w, xv.w); FMA2(o01[it], xp, w01[3]); FMA2(o23[it], xp, w23[3]);
            }
        }
        #pragma unroll
        for (int it = 0; it < 8; it++) {
            int c = it*32 + cslot;
            float a0, a1;
            float* obase = out + ((size_t)(n*CC + c)*64 + 2*hh)*64 + 2*ww;
            UNPACK2(a0, a1, o01[it]);
            *(float2*)obase = make_float2(a0, a1);
            UNPACK2(a0, a1, o23[it]);
            *(float2*)(obase + 64) = make_float2(a0, a1);
        }
    }
}

extern "C" void kernel_launch(void* const* d_in, const int* in_sizes, int n_in,
                              void* d_out, int out_size)
{
    (void)in_sizes; (void)n_in; (void)out_size;
    const float* x  = (const float*)d_in[0];
    const float* wk = (const float*)d_in[1];
    const float* ws = (const float*)d_in[2];
    float* out = (float*)d_out;

    prep_wkey<<<(64*WKP_W + 255)/256, 256>>>(wk);
    cudaFuncSetAttribute(frac_fused_kernel,
                         cudaFuncAttributeMaxDynamicSharedMemorySize, SMEM_BYTES);
    frac_fused_kernel<<<dim3(4, 32, 16), 256, SMEM_BYTES>>>(x, ws, out);
}